// round 4
// baseline (speedup 1.0000x reference)
#include <cuda_runtime.h>
#include <math.h>

// Problem constants
#define B_BATCH   32
#define NPTS      65536
#define NCH       14
#define CHUNKS    64
#define ROWS_PER_BLOCK (NPTS / CHUNKS)          // 1024
#define THREADS   256
#define ROWS_PER_THREAD (ROWS_PER_BLOCK / THREADS) // 4

#define EPS_D       1e-06
#define MAX_RATIO_D 1000000.0
#define CLAMP_ABS_D 1000000.0

// Per-(batch,chunk) partial moments: [B][CHUNKS][9] doubles (static scratch; no alloc)
__device__ double g_part[B_BATCH * CHUNKS * 9];

// ---------------------------------------------------------------------------
// Kernel 1: accumulate 9 raw moments per (batch, chunk) block.
// Deterministic: fixed per-thread serial order + fixed tree reduction.
// ---------------------------------------------------------------------------
__global__ __launch_bounds__(THREADS) void moments_kernel(const float* __restrict__ g)
{
    const int chunk = blockIdx.x;
    const int b     = blockIdx.y;
    const int tid   = threadIdx.x;

    const float* base = g + ((size_t)b * NPTS + (size_t)chunk * ROWS_PER_BLOCK) * NCH;

    float sx = 0.f, sy = 0.f, sz = 0.f;
    float sxx = 0.f, sxy = 0.f, sxz = 0.f, syy = 0.f, syz = 0.f, szz = 0.f;

    // 4 rows per thread, stride THREADS for coalescing. 12 independent loads
    // in flight after unroll -> good MLP against ~577cyc DRAM latency.
    float x[ROWS_PER_THREAD], y[ROWS_PER_THREAD], z[ROWS_PER_THREAD];
#pragma unroll
    for (int k = 0; k < ROWS_PER_THREAD; k++) {
        const float* r = base + (size_t)(k * THREADS + tid) * NCH;
        x[k] = __ldg(r + 0);
        y[k] = __ldg(r + 1);
        z[k] = __ldg(r + 2);
    }
#pragma unroll
    for (int k = 0; k < ROWS_PER_THREAD; k++) {
        sx += x[k]; sy += y[k]; sz += z[k];
        sxx = fmaf(x[k], x[k], sxx);
        sxy = fmaf(x[k], y[k], sxy);
        sxz = fmaf(x[k], z[k], sxz);
        syy = fmaf(y[k], y[k], syy);
        syz = fmaf(y[k], z[k], syz);
        szz = fmaf(z[k], z[k], szz);
    }

    float v[9] = { sx, sy, sz, sxx, sxy, sxz, syy, syz, szz };

    // Warp tree reduce (deterministic)
#pragma unroll
    for (int o = 16; o > 0; o >>= 1) {
#pragma unroll
        for (int i = 0; i < 9; i++)
            v[i] += __shfl_down_sync(0xffffffffu, v[i], o);
    }

    __shared__ float sm[8][9];
    const int warp = tid >> 5, lane = tid & 31;
    if (lane == 0) {
#pragma unroll
        for (int i = 0; i < 9; i++) sm[warp][i] = v[i];
    }
    __syncthreads();

    if (warp == 0) {
        float w[9];
#pragma unroll
        for (int i = 0; i < 9; i++) w[i] = (lane < 8) ? sm[lane][i] : 0.f;
#pragma unroll
        for (int o = 4; o > 0; o >>= 1) {
#pragma unroll
            for (int i = 0; i < 9; i++)
                w[i] += __shfl_down_sync(0xffffffffu, w[i], o);
        }
        if (lane == 0) {
            double* dst = &g_part[(size_t)(b * CHUNKS + chunk) * 9];
#pragma unroll
            for (int i = 0; i < 9; i++) dst[i] = (double)w[i];
        }
    }
}

// ---------------------------------------------------------------------------
// Kernel 2: per-batch covariance -> sanitize -> symmetric 3x3 eigenvalues
// (closed-form, double) -> -mean(log(clamp(max/min, 1, 1e6)))
// ---------------------------------------------------------------------------
__device__ __forceinline__ double sanitize_d(double v)
{
    if (isnan(v)) return 0.0;
    if (v >  CLAMP_ABS_D) return  CLAMP_ABS_D;
    if (v < -CLAMP_ABS_D) return -CLAMP_ABS_D;
    return v;
}

__global__ __launch_bounds__(THREADS) void finalize_kernel(float* __restrict__ out)
{
    __shared__ double red[B_BATCH * 8][9];  // 18 KB
    __shared__ double lr[B_BATCH];

    const int t    = threadIdx.x;      // 256 = 32 batches x 8 partial-summers
    const int b    = t >> 3;
    const int part = t & 7;

    double a[9];
#pragma unroll
    for (int i = 0; i < 9; i++) a[i] = 0.0;

    // Fixed order per thread -> deterministic
    for (int c = part; c < CHUNKS; c += 8) {
        const double* src = &g_part[(size_t)(b * CHUNKS + c) * 9];
#pragma unroll
        for (int i = 0; i < 9; i++) a[i] += src[i];
    }
#pragma unroll
    for (int i = 0; i < 9; i++) red[t][i] = a[i];
    __syncthreads();

    for (int s = 4; s > 0; s >>= 1) {
        if (part < s) {
#pragma unroll
            for (int i = 0; i < 9; i++) red[t][i] += red[t + s][i];
        }
        __syncthreads();
    }

    if (part == 0) {
        const double invN = 1.0 / (double)NPTS;
        const double mx = red[t][0] * invN;
        const double my = red[t][1] * invN;
        const double mz = red[t][2] * invN;

        double c00 = sanitize_d(red[t][3] * invN - mx * mx);
        double c01 = sanitize_d(red[t][4] * invN - mx * my);
        double c02 = sanitize_d(red[t][5] * invN - mx * mz);
        double c11 = sanitize_d(red[t][6] * invN - my * my);
        double c12 = sanitize_d(red[t][7] * invN - my * mz);
        double c22 = sanitize_d(red[t][8] * invN - mz * mz);
        // Matrix already symmetric; 0.5*(C + C^T) is identity here.

        // Closed-form eigenvalues of symmetric 3x3 (trigonometric method)
        double emax, emin;
        const double p1 = c01 * c01 + c02 * c02 + c12 * c12;
        if (p1 == 0.0) {
            emax = fmax(c00, fmax(c11, c22));
            emin = fmin(c00, fmin(c11, c22));
        } else {
            const double q  = (c00 + c11 + c22) / 3.0;
            const double p2 = (c00 - q) * (c00 - q) + (c11 - q) * (c11 - q) +
                              (c22 - q) * (c22 - q) + 2.0 * p1;
            const double p  = sqrt(p2 / 6.0);
            const double ip = 1.0 / p;
            const double b00 = (c00 - q) * ip, b11 = (c11 - q) * ip, b22 = (c22 - q) * ip;
            const double b01 = c01 * ip, b02 = c02 * ip, b12 = c12 * ip;
            double detB = b00 * (b11 * b22 - b12 * b12)
                        - b01 * (b01 * b22 - b12 * b02)
                        + b02 * (b01 * b12 - b11 * b02);
            double r = detB * 0.5;
            r = fmin(1.0, fmax(-1.0, r));
            const double phi = acos(r) / 3.0;
            emax = q + 2.0 * p * cos(phi);
            emin = q + 2.0 * p * cos(phi + 2.0943951023931953); // + 2*pi/3
        }

        const double max_e = fmax(sanitize_d(emax), EPS_D);
        const double min_e = fmax(sanitize_d(emin), EPS_D);
        double ratio = max_e / min_e;
        ratio = fmin(MAX_RATIO_D, fmax(1.0, ratio));
        lr[b] = log(ratio);
    }
    __syncthreads();

    if (t == 0) {
        double s = 0.0;
        for (int i = 0; i < B_BATCH; i++) s += lr[i];
        out[0] = (float)(-s / (double)B_BATCH);
    }
}

// ---------------------------------------------------------------------------
extern "C" void kernel_launch(void* const* d_in, const int* in_sizes, int n_in,
                              void* d_out, int out_size)
{
    (void)in_sizes; (void)n_in; (void)out_size;
    const float* gaussians = (const float*)d_in[0];
    float* out = (float*)d_out;

    dim3 grid(CHUNKS, B_BATCH);
    moments_kernel<<<grid, THREADS>>>(gaussians);
    finalize_kernel<<<1, THREADS>>>(out);
}